// round 13
// baseline (speedup 1.0000x reference)
#include <cuda_runtime.h>
#include <cuda_bf16.h>
#include <cuda_fp16.h>
#include <math.h>

// ---------------- problem constants ----------------
#define NN 100000          // nodes
#define NE 1600000         // edges
#define NG 512             // graphs
#define F1 128             // IN_F == H1
#define F2 256             // H2
#define NGRP 16
#define NFAM 10

#define SB 512
#define NBLK ((NN + SB - 1) / SB)   // 196 scan blocks
#define INIT_N (NG * F2)

// HMMA GEMM1 geometry
#define ASTRIDE 136                     // 128 + 8 halves pad
#define HSMEM_BYTES (2 * 128 * ASTRIDE * 2)   // A + B panels, fp16

// ---------------- device scratch (no allocations allowed) ----------------
__device__ __half g_xw1h[ (size_t)NN * F1 ];  // x @ W1          (fp16)
__device__ __half g_r1h [ (size_t)NN * F1 ];  // relu(A*xw1+b1)  (fp16)
__device__ float  g_psum[ NG * F1 ];
__device__ float  g_dinv[ NN ];
__device__ float  g_cnts[ NG ];
__device__ int    g_batch[ NN ];
__device__ int    g_is64;
__device__ int    g_degi  [ NN ];
__device__ int    g_off   [ NN ];
__device__ int    g_cursor[ NN ];
__device__ unsigned long long g_scanstate[ NBLK ];
__device__ int2   g_csr   [ NE ];             // (src, coef bits) interleaved

// ---------------- fused dtype-detect + init ----------------
__global__ void k_dinit(const unsigned int* __restrict__ e) {
    int i = blockIdx.x * blockDim.x + threadIdx.x;
    if (blockIdx.x == 0 && threadIdx.x < 32) {
        unsigned int v = e[2 * threadIdx.x + 1];
        unsigned int m = __ballot_sync(0xffffffffu, v != 0u);
        if (threadIdx.x == 0) g_is64 = (m == 0u) ? 1 : 0;
    }
    if (i < NN) g_degi[i] = 0;
    if (i < NG * F1) g_psum[i] = 0.0f;
    if (i < NG) g_cnts[i] = 0.0f;
    if (i < NBLK) g_scanstate[i] = 0ULL;
}

// ---------------- degree count (dst only, 2 edges/thread, vectorized) ----------
__global__ void k_deg(const int* __restrict__ in) {
    int t = blockIdx.x * blockDim.x + threadIdx.x;
    int e2 = t * 2;
    if (e2 >= NE) return;
    int d0, d1;
    if (g_is64) {
        int4 v = *(const int4*)(in + 2 * (NE + e2));
        d0 = v.x; d1 = v.z;
    } else {
        int2 v = *(const int2*)(in + NE + e2);
        d0 = v.x; d1 = v.y;
    }
    atomicAdd(&g_degi[d0], 1);
    atomicAdd(&g_degi[d1], 1);
}

__global__ void k_conv_batch(const int* __restrict__ in) {
    int i = blockIdx.x * blockDim.x + threadIdx.x;
    if (i >= NN) return;
    g_batch[i] = g_is64 ? in[2 * i] : in[i];
}

// ---------------- single-pass decoupled-lookback scan (+ dinv, cursor) ---------
// flag (bits 32..): 0 = not ready, 1 = aggregate, 2 = inclusive prefix.
__global__ void k_scan() {
    __shared__ int sh[SB];
    __shared__ int s_prefix;
    int b = blockIdx.x;
    int i = b * SB + threadIdx.x;
    int v = (i < NN) ? g_degi[i] : 0;
    sh[threadIdx.x] = v;
    __syncthreads();
    for (int off = 1; off < SB; off <<= 1) {
        int t = (threadIdx.x >= off) ? sh[threadIdx.x - off] : 0;
        __syncthreads();
        sh[threadIdx.x] += t;
        __syncthreads();
    }
    int incl = sh[threadIdx.x];
    int aggregate = sh[SB - 1];

    if (threadIdx.x == 0) {
        if (b == 0) {
            atomicExch(&g_scanstate[0],
                       (2ULL << 32) | (unsigned long long)(unsigned)aggregate);
            s_prefix = 0;
        } else {
            atomicExch(&g_scanstate[b],
                       (1ULL << 32) | (unsigned long long)(unsigned)aggregate);
            int run = 0;
            int p = b - 1;
            while (true) {
                unsigned long long st = atomicAdd(&g_scanstate[p], 0ULL);
                unsigned flag = (unsigned)(st >> 32);
                if (flag == 0u) continue;             // spin
                run += (int)(unsigned)st;
                if (flag == 2u) break;
                p--;
            }
            atomicExch(&g_scanstate[b],
                       (2ULL << 32) | (unsigned long long)(unsigned)(run + aggregate));
            s_prefix = run;
        }
    }
    __syncthreads();

    if (i < NN) {
        int excl = s_prefix + incl - v;
        g_off[i] = excl;
        g_cursor[i] = excl;
        g_dinv[i] = rsqrtf((float)(g_degi[i] + 1));
    }
}

// ---------------- CSR fill: 2 edges/thread, reads raw edge list ----------------
__global__ void k_fill(const int* __restrict__ in) {
    int t = blockIdx.x * blockDim.x + threadIdx.x;
    int e2 = t * 2;
    if (e2 >= NE) return;
    int s0, s1, d0, d1;
    if (g_is64) {
        int4 sv = *(const int4*)(in + 2 * e2);
        int4 dv = *(const int4*)(in + 2 * (NE + e2));
        s0 = sv.x; s1 = sv.z; d0 = dv.x; d1 = dv.z;
    } else {
        int2 sv = *(const int2*)(in + e2);
        int2 dv = *(const int2*)(in + NE + e2);
        s0 = sv.x; s1 = sv.y; d0 = dv.x; d1 = dv.y;
    }
    float c0 = g_dinv[s0] * g_dinv[d0];
    float c1 = g_dinv[s1] * g_dinv[d1];
    int sl0 = atomicAdd(&g_cursor[d0], 1);
    g_csr[sl0] = make_int2(s0, __float_as_int(c0));
    int sl1 = atomicAdd(&g_cursor[d1], 1);
    g_csr[sl1] = make_int2(s1, __float_as_int(c1));
}

// ---------------- HMMA GEMM1: C[M,128] = A[M,128] * B[128,128], fp16 out --------
__launch_bounds__(256)
__global__ void k_hgemm(const float* __restrict__ A, const float* __restrict__ B,
                        __half* __restrict__ C, int M)
{
    extern __shared__ __half smem[];
    __half* As  = smem;                 // [128][ASTRIDE]
    __half* Bsm = smem + 128 * ASTRIDE; // [128][ASTRIDE]

    const int tid  = threadIdx.x;
    const int lane = tid & 31;
    const int wid  = tid >> 5;
    const int wm   = wid >> 1;
    const int wn   = wid & 1;
    const int row0 = blockIdx.x * 128;

#pragma unroll
    for (int i = 0; i < 16; i++) {
        int idx = tid + i * 256;
        int row = idx >> 5;
        int c4  = idx & 31;
        float4 v = make_float4(0.f, 0.f, 0.f, 0.f);
        if (row0 + row < M)
            v = *(const float4*)(A + (size_t)(row0 + row) * 128 + c4 * 4);
        __half2 h01 = __floats2half2_rn(v.x, v.y);
        __half2 h23 = __floats2half2_rn(v.z, v.w);
        uint2 pk;
        pk.x = *(unsigned int*)&h01;
        pk.y = *(unsigned int*)&h23;
        *(uint2*)(As + row * ASTRIDE + c4 * 4) = pk;

        float4 w = *(const float4*)(B + (size_t)row * 128 + c4 * 4);
        __half2 w01 = __floats2half2_rn(w.x, w.y);
        __half2 w23 = __floats2half2_rn(w.z, w.w);
        uint2 pw;
        pw.x = *(unsigned int*)&w01;
        pw.y = *(unsigned int*)&w23;
        *(uint2*)(Bsm + row * ASTRIDE + c4 * 4) = pw;
    }
    __syncthreads();

    float acc[2][8][4];
#pragma unroll
    for (int mt = 0; mt < 2; mt++)
#pragma unroll
        for (int nt = 0; nt < 8; nt++)
#pragma unroll
            for (int r = 0; r < 4; r++) acc[mt][nt][r] = 0.0f;

#pragma unroll
    for (int kc = 0; kc < 8; kc++) {
        int k0 = kc * 16;
        unsigned int a[2][4];
#pragma unroll
        for (int mt = 0; mt < 2; mt++) {
            int r = wm * 32 + mt * 16 + (lane & 15);
            int c = k0 + (lane >> 4) * 8;
            unsigned int addr = (unsigned int)__cvta_generic_to_shared(As + r * ASTRIDE + c);
            asm volatile("ldmatrix.sync.aligned.m8n8.x4.shared.b16 {%0,%1,%2,%3}, [%4];"
                         : "=r"(a[mt][0]), "=r"(a[mt][1]), "=r"(a[mt][2]), "=r"(a[mt][3])
                         : "r"(addr));
        }
        unsigned int b[8][2];
#pragma unroll
        for (int p = 0; p < 4; p++) {
            int r = k0 + (lane & 15);
            int c = wn * 64 + p * 16 + (lane >> 4) * 8;
            unsigned int addr = (unsigned int)__cvta_generic_to_shared(Bsm + r * ASTRIDE + c);
            unsigned int r0, r1, r2, r3;
            asm volatile("ldmatrix.sync.aligned.m8n8.x4.trans.shared.b16 {%0,%1,%2,%3}, [%4];"
                         : "=r"(r0), "=r"(r1), "=r"(r2), "=r"(r3)
                         : "r"(addr));
            b[p * 2][0] = r0; b[p * 2][1] = r1;
            b[p * 2 + 1][0] = r2; b[p * 2 + 1][1] = r3;
        }
#pragma unroll
        for (int mt = 0; mt < 2; mt++)
#pragma unroll
            for (int nt = 0; nt < 8; nt++)
                asm volatile("mma.sync.aligned.m16n8k16.row.col.f32.f16.f16.f32 "
                             "{%0,%1,%2,%3}, {%4,%5,%6,%7}, {%8,%9}, {%0,%1,%2,%3};"
                             : "+f"(acc[mt][nt][0]), "+f"(acc[mt][nt][1]),
                               "+f"(acc[mt][nt][2]), "+f"(acc[mt][nt][3])
                             : "r"(a[mt][0]), "r"(a[mt][1]), "r"(a[mt][2]), "r"(a[mt][3]),
                               "r"(b[nt][0]), "r"(b[nt][1]));
    }

    const int g  = lane >> 2;
    const int t4 = lane & 3;
#pragma unroll
    for (int mt = 0; mt < 2; mt++) {
#pragma unroll
        for (int nt = 0; nt < 8; nt++) {
            int row = row0 + wm * 32 + mt * 16 + g;
            int col = wn * 64 + nt * 8 + t4 * 2;
            if (row < M) {
                __half2 h = __floats2half2_rn(acc[mt][nt][0], acc[mt][nt][1]);
                *(__half2*)(C + (size_t)row * 128 + col) = h;
            }
            if (row + 8 < M) {
                __half2 h = __floats2half2_rn(acc[mt][nt][2], acc[mt][nt][3]);
                *(__half2*)(C + (size_t)(row + 8) * 128 + col) = h;
            }
        }
    }
}

// ---------------- layer-1 gather (warp per node): r1 = relu(A_hat*xw1 + b1) -----
__launch_bounds__(256)
__global__ void k_gather1(const __half* __restrict__ in, const float* __restrict__ bias,
                          __half* __restrict__ outh)
{
    int d = (blockIdx.x * 256 + threadIdx.x) >> 5;
    if (d >= NN) return;
    int lane = threadIdx.x & 31;
    int beg = g_off[d];
    int end = beg + g_degi[d];

    float4 acc = make_float4(0.f, 0.f, 0.f, 0.f);

#define LOAD4(sidx, f01, f23)                                               \
    {                                                                       \
        uint2 u = *(const uint2*)(in + (size_t)(sidx) * 128 + lane * 4);    \
        f01 = __half22float2(*(__half2*)&u.x);                              \
        f23 = __half22float2(*(__half2*)&u.y);                              \
    }

    int j = beg;
    for (; j + 3 < end; j += 4) {
        int2 e0 = g_csr[j],     e1 = g_csr[j + 1];
        int2 e2 = g_csr[j + 2], e3 = g_csr[j + 3];
        float c0 = __int_as_float(e0.y), c1 = __int_as_float(e1.y);
        float c2 = __int_as_float(e2.y), c3 = __int_as_float(e3.y);
        float2 a01, a23, b01, b23, e01, e23, f01, f23;
        LOAD4(e0.x, a01, a23); LOAD4(e1.x, b01, b23);
        LOAD4(e2.x, e01, e23); LOAD4(e3.x, f01, f23);
        acc.x += c0 * a01.x + c1 * b01.x + c2 * e01.x + c3 * f01.x;
        acc.y += c0 * a01.y + c1 * b01.y + c2 * e01.y + c3 * f01.y;
        acc.z += c0 * a23.x + c1 * b23.x + c2 * e23.x + c3 * f23.x;
        acc.w += c0 * a23.y + c1 * b23.y + c2 * e23.y + c3 * f23.y;
    }
    for (; j < end; j++) {
        int2 e0 = g_csr[j];
        float c0 = __int_as_float(e0.y);
        float2 a01, a23;
        LOAD4(e0.x, a01, a23);
        acc.x += c0 * a01.x; acc.y += c0 * a01.y;
        acc.z += c0 * a23.x; acc.w += c0 * a23.y;
    }

    // self loop
    {
        float dv = g_dinv[d];
        float c = dv * dv;
        float2 a01, a23;
        LOAD4(d, a01, a23);
        acc.x += c * a01.x; acc.y += c * a01.y;
        acc.z += c * a23.x; acc.w += c * a23.y;
    }

    float4 bb = *(const float4*)(bias + lane * 4);
    acc.x = fmaxf(acc.x + bb.x, 0.f);
    acc.y = fmaxf(acc.y + bb.y, 0.f);
    acc.z = fmaxf(acc.z + bb.z, 0.f);
    acc.w = fmaxf(acc.w + bb.w, 0.f);

    __half2 h0 = __floats2half2_rn(acc.x, acc.y);
    __half2 h1 = __floats2half2_rn(acc.z, acc.w);
    uint2 pk;
    pk.x = *(unsigned int*)&h0;
    pk.y = *(unsigned int*)&h1;
    *(uint2*)(outh + (size_t)d * 128 + lane * 4) = pk;
#undef LOAD4
}

// ---------------- fused layer-2 gather + pool ----------------
__launch_bounds__(256)
__global__ void k_gpool(const __half* __restrict__ r1)
{
    int warp = threadIdx.x >> 5;
    int lane = threadIdx.x & 31;
    int n0 = blockIdx.x * 64 + warp * 8;
    if (n0 >= NN) return;
    int n1 = min(n0 + 8, NN);

    int curg = g_batch[n0];
    float4 acc = make_float4(0.f, 0.f, 0.f, 0.f);
    int cnt = 0;

#define LOAD4(sidx, f01, f23)                                               \
    {                                                                       \
        uint2 u = *(const uint2*)(r1 + (size_t)(sidx) * 128 + lane * 4);    \
        f01 = __half22float2(*(__half2*)&u.x);                              \
        f23 = __half22float2(*(__half2*)&u.y);                              \
    }

    for (int n = n0; n < n1; n++) {
        int gg = g_batch[n];
        if (gg != curg) {
            float* ps = g_psum + curg * F1 + lane * 4;
            atomicAdd(ps + 0, acc.x); atomicAdd(ps + 1, acc.y);
            atomicAdd(ps + 2, acc.z); atomicAdd(ps + 3, acc.w);
            if (lane == 0) atomicAdd(&g_cnts[curg], (float)cnt);
            acc = make_float4(0.f, 0.f, 0.f, 0.f);
            cnt = 0; curg = gg;
        }

        int beg = g_off[n];
        int end = beg + g_degi[n];
        int j = beg;
        for (; j + 3 < end; j += 4) {
            int2 e0 = g_csr[j],     e1 = g_csr[j + 1];
            int2 e2 = g_csr[j + 2], e3 = g_csr[j + 3];
            float c0 = __int_as_float(e0.y), c1 = __int_as_float(e1.y);
            float c2 = __int_as_float(e2.y), c3 = __int_as_float(e3.y);
            float2 a01, a23, b01, b23, e01, e23, f01, f23;
            LOAD4(e0.x, a01, a23); LOAD4(e1.x, b01, b23);
            LOAD4(e2.x, e01, e23); LOAD4(e3.x, f01, f23);
            acc.x += c0 * a01.x + c1 * b01.x + c2 * e01.x + c3 * f01.x;
            acc.y += c0 * a01.y + c1 * b01.y + c2 * e01.y + c3 * f01.y;
            acc.z += c0 * a23.x + c1 * b23.x + c2 * e23.x + c3 * f23.x;
            acc.w += c0 * a23.y + c1 * b23.y + c2 * e23.y + c3 * f23.y;
        }
        for (; j < end; j++) {
            int2 e0 = g_csr[j];
            float c0 = __int_as_float(e0.y);
            float2 a01, a23;
            LOAD4(e0.x, a01, a23);
            acc.x += c0 * a01.x; acc.y += c0 * a01.y;
            acc.z += c0 * a23.x; acc.w += c0 * a23.y;
        }
        // self loop
        {
            float dv = g_dinv[n];
            float c = dv * dv;
            float2 a01, a23;
            LOAD4(n, a01, a23);
            acc.x += c * a01.x; acc.y += c * a01.y;
            acc.z += c * a23.x; acc.w += c * a23.y;
        }
        cnt++;
    }
#undef LOAD4

    float* ps = g_psum + curg * F1 + lane * 4;
    atomicAdd(ps + 0, acc.x); atomicAdd(ps + 1, acc.y);
    atomicAdd(ps + 2, acc.z); atomicAdd(ps + 3, acc.w);
    if (lane == 0) atomicAdd(&g_cnts[curg], (float)cnt);
}

// ---------------- fused: pooled@W2+b2 then heads ----------------
__global__ void k_w2head(const float* __restrict__ W2, const float* __restrict__ b2,
                         const float* __restrict__ Wg, const float* __restrict__ bg,
                         const float* __restrict__ Wf, const float* __restrict__ bf,
                         float* __restrict__ out)
{
    __shared__ float p[F1];
    __shared__ float p2[F2];
    int b = blockIdx.x, t = threadIdx.x;          // 256 threads
    float cnt = g_cnts[b];
    float inv = 1.0f / fmaxf(cnt, 1.0f);
    if (t < F1) p[t] = g_psum[b * F1 + t] * inv;
    __syncthreads();
    float a = (cnt > 0.f) ? b2[t] : 0.0f;         // empty-graph: pooled stays 0
#pragma unroll 4
    for (int d = 0; d < F1; d++) a += p[d] * W2[d * F2 + t];
    p2[t] = a;
    __syncthreads();
    if (t < NGRP) {
        float s = bg[t];
        for (int d = 0; d < F2; d++) s += p2[d] * Wg[d * NGRP + t];
        out[b * NGRP + t] = s;
    } else if (t >= 64 && t < 64 + NGRP * NFAM) {
        int u = t - 64;
        int grp = u / NFAM, f = u - grp * NFAM;
        float s = bf[grp * NFAM + f];
        for (int d = 0; d < F2; d++) s += p2[d] * Wf[(size_t)grp * F2 * NFAM + d * NFAM + f];
        out[NG * NGRP + (size_t)grp * NG * NFAM + b * NFAM + f] = s;
    }
}

// ---------------- launch ----------------
extern "C" void kernel_launch(void* const* d_in, const int* in_sizes, int n_in,
                              void* d_out, int out_size)
{
    const float* x    = (const float*)d_in[0];
    const void*  eidx = d_in[1];
    const void*  batc = d_in[2];
    const float* W1   = (const float*)d_in[3];
    const float* b1   = (const float*)d_in[4];
    const float* W2   = (const float*)d_in[5];
    const float* b2   = (const float*)d_in[6];
    const float* Wg   = (const float*)d_in[7];
    const float* bg   = (const float*)d_in[8];
    const float* Wf   = (const float*)d_in[9];
    const float* bf   = (const float*)d_in[10];
    float* out = (float*)d_out;

    __half *xw1h, *r1h;
    cudaGetSymbolAddress((void**)&xw1h, g_xw1h);
    cudaGetSymbolAddress((void**)&r1h,  g_r1h);

    cudaFuncSetAttribute(k_hgemm, cudaFuncAttributeMaxDynamicSharedMemorySize, HSMEM_BYTES);

    // side stream + events (created once, outside capture; identical launch
    // sequence every call -> deterministic work).
    static cudaStream_t sB = nullptr;
    static cudaEvent_t evFork = nullptr, evDet = nullptr, evJoin = nullptr;
    if (sB == nullptr) {
        cudaStreamCreateWithFlags(&sB, cudaStreamNonBlocking);
        cudaEventCreateWithFlags(&evFork, cudaEventDisableTiming);
        cudaEventCreateWithFlags(&evDet,  cudaEventDisableTiming);
        cudaEventCreateWithFlags(&evJoin, cudaEventDisableTiming);
    }

    // ---- fork: side stream runs GEMM1 (independent of graph build) ----
    cudaEventRecord(evFork, 0);
    cudaStreamWaitEvent(sB, evFork, 0);
    k_hgemm<<<(NN + 127) / 128, 256, HSMEM_BYTES, sB>>>(x, W1, xw1h, NN);

    // ---- main stream: fused detect+init, then CSR build chain ----
    k_dinit<<<(INIT_N + 255) / 256, 256>>>((const unsigned int*)eidx);
    cudaEventRecord(evDet, 0);
    k_deg<<<(NE / 2 + 255) / 256, 256>>>((const int*)eidx);
    k_scan<<<NBLK, SB>>>();          // single-pass lookback; also cursor + dinv
    k_fill<<<(NE / 2 + 255) / 256, 256>>>((const int*)eidx);

    // side stream: batch convert (needs detect result only)
    cudaStreamWaitEvent(sB, evDet, 0);
    k_conv_batch<<<(NN + 255) / 256, 256, 0, sB>>>((const int*)batc);
    cudaEventRecord(evJoin, sB);

    // ---- join: gathers need xw1h + batch (sB) and CSR (main) ----
    cudaStreamWaitEvent(0, evJoin, 0);

    // layer 1 gather (+relu, fp16 out), then fused layer-2 gather+pool
    k_gather1<<<(NN * 32 + 255) / 256, 256>>>(xw1h, b1, r1h);
    k_gpool<<<(NN + 63) / 64, 256>>>(r1h);

    // fused W2 + heads
    k_w2head<<<NG, 256>>>(W2, b2, Wg, bg, Wf, bf, out);
}

// round 14
// speedup vs baseline: 1.1795x; 1.1795x over previous
#include <cuda_runtime.h>
#include <cuda_bf16.h>
#include <cuda_fp16.h>
#include <math.h>

// ---------------- problem constants ----------------
#define NN 100000          // nodes
#define NE 1600000         // edges
#define NG 512             // graphs
#define F1 128             // IN_F == H1
#define F2 256             // H2
#define NGRP 16
#define NFAM 10

#define SB 512
#define NBLK ((NN + SB - 1) / SB)   // 196 scan blocks
#define INIT_N (NG * F2)

// HMMA GEMM1 geometry
#define ASTRIDE 136                     // 128 + 8 halves pad
#define HSMEM_BYTES (2 * 128 * ASTRIDE * 2)   // A + B panels, fp16

// ---------------- device scratch (no allocations allowed) ----------------
__device__ __half g_xw1h[ (size_t)NN * F1 ];  // x @ W1          (fp16)
__device__ __half g_r1h [ (size_t)NN * F1 ];  // relu(A*xw1+b1)  (fp16)
__device__ float  g_psum[ NG * F1 ];
__device__ float  g_dinv[ NN ];
__device__ float  g_cnts[ NG ];
__device__ int    g_batch[ NN ];
__device__ int    g_is64;
__device__ int    g_degi  [ NN ];
__device__ int    g_off   [ NN ];
__device__ int    g_cursor[ NN ];
__device__ int    g_bsum  [ 256 ];
__device__ int2   g_csr   [ NE ];             // (src, coef bits) interleaved

// ---------------- dtype detection (one warp, parallel loads) ----------------
__global__ void k_detect(const unsigned int* __restrict__ e) {
    unsigned int v = e[2 * threadIdx.x + 1];
    unsigned int m = __ballot_sync(0xffffffffu, v != 0u);
    if (threadIdx.x == 0) g_is64 = (m == 0u) ? 1 : 0;
}

// ---------------- init ----------------
__global__ void k_init() {
    int i = blockIdx.x * blockDim.x + threadIdx.x;
    if (i < NN) g_degi[i] = 0;
    if (i < NG * F1) g_psum[i] = 0.0f;
    if (i < NG) g_cnts[i] = 0.0f;
}

// ---------------- degree count (dst only, 2 edges/thread, vectorized) ----------
__global__ void k_deg(const int* __restrict__ in) {
    int t = blockIdx.x * blockDim.x + threadIdx.x;
    int e2 = t * 2;
    if (e2 >= NE) return;
    int d0, d1;
    if (g_is64) {
        int4 v = *(const int4*)(in + 2 * (NE + e2));
        d0 = v.x; d1 = v.z;
    } else {
        int2 v = *(const int2*)(in + NE + e2);
        d0 = v.x; d1 = v.y;
    }
    atomicAdd(&g_degi[d0], 1);
    atomicAdd(&g_degi[d1], 1);
}

__global__ void k_conv_batch(const int* __restrict__ in) {
    int i = blockIdx.x * blockDim.x + threadIdx.x;
    if (i >= NN) return;
    g_batch[i] = g_is64 ? in[2 * i] : in[i];
}

// ---------------- exclusive scan over g_degi -> g_off (+ dinv fold) ------------
__global__ void k_scan_local() {
    __shared__ int sh[SB];
    int i = blockIdx.x * SB + threadIdx.x;
    int v = (i < NN) ? g_degi[i] : 0;
    sh[threadIdx.x] = v;
    __syncthreads();
    for (int off = 1; off < SB; off <<= 1) {
        int t = (threadIdx.x >= off) ? sh[threadIdx.x - off] : 0;
        __syncthreads();
        sh[threadIdx.x] += t;
        __syncthreads();
    }
    if (i < NN) g_off[i] = sh[threadIdx.x] - v;
    if (threadIdx.x == SB - 1) g_bsum[blockIdx.x] = sh[SB - 1];
}

__global__ void k_scan_bsum() {
    __shared__ int sh[256];
    int t = threadIdx.x;
    int v = (t < NBLK) ? g_bsum[t] : 0;
    sh[t] = v;
    __syncthreads();
    for (int off = 1; off < 256; off <<= 1) {
        int u = (t >= off) ? sh[t - off] : 0;
        __syncthreads();
        sh[t] += u;
        __syncthreads();
    }
    if (t < NBLK) g_bsum[t] = sh[t] - v;
}

__global__ void k_scan_add() {
    int i = blockIdx.x * SB + threadIdx.x;
    if (i < NN) {
        int o = g_off[i] + g_bsum[blockIdx.x];
        g_off[i] = o;
        g_cursor[i] = o;
        g_dinv[i] = rsqrtf((float)(g_degi[i] + 1));
    }
}

// ---------------- CSR fill: 2 edges/thread, reads raw edge list ----------------
__global__ void k_fill(const int* __restrict__ in) {
    int t = blockIdx.x * blockDim.x + threadIdx.x;
    int e2 = t * 2;
    if (e2 >= NE) return;
    int s0, s1, d0, d1;
    if (g_is64) {
        int4 sv = *(const int4*)(in + 2 * e2);
        int4 dv = *(const int4*)(in + 2 * (NE + e2));
        s0 = sv.x; s1 = sv.z; d0 = dv.x; d1 = dv.z;
    } else {
        int2 sv = *(const int2*)(in + e2);
        int2 dv = *(const int2*)(in + NE + e2);
        s0 = sv.x; s1 = sv.y; d0 = dv.x; d1 = dv.y;
    }
    float c0 = g_dinv[s0] * g_dinv[d0];
    float c1 = g_dinv[s1] * g_dinv[d1];
    int sl0 = atomicAdd(&g_cursor[d0], 1);
    g_csr[sl0] = make_int2(s0, __float_as_int(c0));
    int sl1 = atomicAdd(&g_cursor[d1], 1);
    g_csr[sl1] = make_int2(s1, __float_as_int(c1));
}

// ---------------- HMMA GEMM1: C[M,128] = A[M,128] * B[128,128], fp16 out --------
__launch_bounds__(256)
__global__ void k_hgemm(const float* __restrict__ A, const float* __restrict__ B,
                        __half* __restrict__ C, int M)
{
    extern __shared__ __half smem[];
    __half* As  = smem;                 // [128][ASTRIDE]
    __half* Bsm = smem + 128 * ASTRIDE; // [128][ASTRIDE]

    const int tid  = threadIdx.x;
    const int lane = tid & 31;
    const int wid  = tid >> 5;
    const int wm   = wid >> 1;
    const int wn   = wid & 1;
    const int row0 = blockIdx.x * 128;

#pragma unroll
    for (int i = 0; i < 16; i++) {
        int idx = tid + i * 256;
        int row = idx >> 5;
        int c4  = idx & 31;
        float4 v = make_float4(0.f, 0.f, 0.f, 0.f);
        if (row0 + row < M)
            v = *(const float4*)(A + (size_t)(row0 + row) * 128 + c4 * 4);
        __half2 h01 = __floats2half2_rn(v.x, v.y);
        __half2 h23 = __floats2half2_rn(v.z, v.w);
        uint2 pk;
        pk.x = *(unsigned int*)&h01;
        pk.y = *(unsigned int*)&h23;
        *(uint2*)(As + row * ASTRIDE + c4 * 4) = pk;

        float4 w = *(const float4*)(B + (size_t)row * 128 + c4 * 4);
        __half2 w01 = __floats2half2_rn(w.x, w.y);
        __half2 w23 = __floats2half2_rn(w.z, w.w);
        uint2 pw;
        pw.x = *(unsigned int*)&w01;
        pw.y = *(unsigned int*)&w23;
        *(uint2*)(Bsm + row * ASTRIDE + c4 * 4) = pw;
    }
    __syncthreads();

    float acc[2][8][4];
#pragma unroll
    for (int mt = 0; mt < 2; mt++)
#pragma unroll
        for (int nt = 0; nt < 8; nt++)
#pragma unroll
            for (int r = 0; r < 4; r++) acc[mt][nt][r] = 0.0f;

#pragma unroll
    for (int kc = 0; kc < 8; kc++) {
        int k0 = kc * 16;
        unsigned int a[2][4];
#pragma unroll
        for (int mt = 0; mt < 2; mt++) {
            int r = wm * 32 + mt * 16 + (lane & 15);
            int c = k0 + (lane >> 4) * 8;
            unsigned int addr = (unsigned int)__cvta_generic_to_shared(As + r * ASTRIDE + c);
            asm volatile("ldmatrix.sync.aligned.m8n8.x4.shared.b16 {%0,%1,%2,%3}, [%4];"
                         : "=r"(a[mt][0]), "=r"(a[mt][1]), "=r"(a[mt][2]), "=r"(a[mt][3])
                         : "r"(addr));
        }
        unsigned int b[8][2];
#pragma unroll
        for (int p = 0; p < 4; p++) {
            int r = k0 + (lane & 15);
            int c = wn * 64 + p * 16 + (lane >> 4) * 8;
            unsigned int addr = (unsigned int)__cvta_generic_to_shared(Bsm + r * ASTRIDE + c);
            unsigned int r0, r1, r2, r3;
            asm volatile("ldmatrix.sync.aligned.m8n8.x4.trans.shared.b16 {%0,%1,%2,%3}, [%4];"
                         : "=r"(r0), "=r"(r1), "=r"(r2), "=r"(r3)
                         : "r"(addr));
            b[p * 2][0] = r0; b[p * 2][1] = r1;
            b[p * 2 + 1][0] = r2; b[p * 2 + 1][1] = r3;
        }
#pragma unroll
        for (int mt = 0; mt < 2; mt++)
#pragma unroll
            for (int nt = 0; nt < 8; nt++)
                asm volatile("mma.sync.aligned.m16n8k16.row.col.f32.f16.f16.f32 "
                             "{%0,%1,%2,%3}, {%4,%5,%6,%7}, {%8,%9}, {%0,%1,%2,%3};"
                             : "+f"(acc[mt][nt][0]), "+f"(acc[mt][nt][1]),
                               "+f"(acc[mt][nt][2]), "+f"(acc[mt][nt][3])
                             : "r"(a[mt][0]), "r"(a[mt][1]), "r"(a[mt][2]), "r"(a[mt][3]),
                               "r"(b[nt][0]), "r"(b[nt][1]));
    }

    const int g  = lane >> 2;
    const int t4 = lane & 3;
#pragma unroll
    for (int mt = 0; mt < 2; mt++) {
#pragma unroll
        for (int nt = 0; nt < 8; nt++) {
            int row = row0 + wm * 32 + mt * 16 + g;
            int col = wn * 64 + nt * 8 + t4 * 2;
            if (row < M) {
                __half2 h = __floats2half2_rn(acc[mt][nt][0], acc[mt][nt][1]);
                *(__half2*)(C + (size_t)row * 128 + col) = h;
            }
            if (row + 8 < M) {
                __half2 h = __floats2half2_rn(acc[mt][nt][2], acc[mt][nt][3]);
                *(__half2*)(C + (size_t)(row + 8) * 128 + col) = h;
            }
        }
    }
}

// ---------------- unrolled edge-batch macro: batch CSR + row loads -------------
// Loads B edges' CSR entries, then B independent 8B row chunks, then consumes.
#define EDGE_BATCH(B, base)                                                   \
    {                                                                         \
        int2 ee[B];                                                           \
        _Pragma("unroll")                                                     \
        for (int k = 0; k < B; k++) ee[k] = g_csr[(base) + k];                \
        uint2 uu[B];                                                          \
        _Pragma("unroll")                                                     \
        for (int k = 0; k < B; k++)                                           \
            uu[k] = *(const uint2*)(in + (size_t)ee[k].x * 128 + lane * 4);   \
        _Pragma("unroll")                                                     \
        for (int k = 0; k < B; k++) {                                         \
            float c = __int_as_float(ee[k].y);                                \
            float2 f01 = __half22float2(*(__half2*)&uu[k].x);                 \
            float2 f23 = __half22float2(*(__half2*)&uu[k].y);                 \
            acc.x += c * f01.x; acc.y += c * f01.y;                           \
            acc.z += c * f23.x; acc.w += c * f23.y;                           \
        }                                                                     \
    }

// ---------------- layer-1 gather (warp per node): r1 = relu(A_hat*xw1 + b1) -----
__launch_bounds__(256)
__global__ void k_gather1(const __half* __restrict__ in, const float* __restrict__ bias,
                          __half* __restrict__ outh)
{
    int d = (blockIdx.x * 256 + threadIdx.x) >> 5;
    if (d >= NN) return;
    int lane = threadIdx.x & 31;
    int beg = g_off[d];
    int end = beg + g_degi[d];

    float4 acc = make_float4(0.f, 0.f, 0.f, 0.f);

    int j = beg;
    for (; j + 7 < end; j += 8) EDGE_BATCH(8, j)
    for (; j + 3 < end; j += 4) EDGE_BATCH(4, j)
    for (; j < end; j++)        EDGE_BATCH(1, j)

    // self loop
    {
        float dv = g_dinv[d];
        float c = dv * dv;
        uint2 u = *(const uint2*)(in + (size_t)d * 128 + lane * 4);
        float2 f01 = __half22float2(*(__half2*)&u.x);
        float2 f23 = __half22float2(*(__half2*)&u.y);
        acc.x += c * f01.x; acc.y += c * f01.y;
        acc.z += c * f23.x; acc.w += c * f23.y;
    }

    float4 bb = *(const float4*)(bias + lane * 4);
    acc.x = fmaxf(acc.x + bb.x, 0.f);
    acc.y = fmaxf(acc.y + bb.y, 0.f);
    acc.z = fmaxf(acc.z + bb.z, 0.f);
    acc.w = fmaxf(acc.w + bb.w, 0.f);

    __half2 h0 = __floats2half2_rn(acc.x, acc.y);
    __half2 h1 = __floats2half2_rn(acc.z, acc.w);
    uint2 pk;
    pk.x = *(unsigned int*)&h0;
    pk.y = *(unsigned int*)&h1;
    *(uint2*)(outh + (size_t)d * 128 + lane * 4) = pk;
}

// ---------------- fused layer-2 gather + pool ----------------
__launch_bounds__(256)
__global__ void k_gpool(const __half* __restrict__ in)
{
    int warp = threadIdx.x >> 5;
    int lane = threadIdx.x & 31;
    int n0 = blockIdx.x * 64 + warp * 8;
    if (n0 >= NN) return;
    int n1 = min(n0 + 8, NN);

    int curg = g_batch[n0];
    float4 acc = make_float4(0.f, 0.f, 0.f, 0.f);
    int cnt = 0;

    for (int n = n0; n < n1; n++) {
        int gg = g_batch[n];
        if (gg != curg) {
            float* ps = g_psum + curg * F1 + lane * 4;
            atomicAdd(ps + 0, acc.x); atomicAdd(ps + 1, acc.y);
            atomicAdd(ps + 2, acc.z); atomicAdd(ps + 3, acc.w);
            if (lane == 0) atomicAdd(&g_cnts[curg], (float)cnt);
            acc = make_float4(0.f, 0.f, 0.f, 0.f);
            cnt = 0; curg = gg;
        }

        int beg = g_off[n];
        int end = beg + g_degi[n];
        int j = beg;
        for (; j + 7 < end; j += 8) EDGE_BATCH(8, j)
        for (; j + 3 < end; j += 4) EDGE_BATCH(4, j)
        for (; j < end; j++)        EDGE_BATCH(1, j)

        // self loop
        {
            float dv = g_dinv[n];
            float c = dv * dv;
            uint2 u = *(const uint2*)(in + (size_t)n * 128 + lane * 4);
            float2 f01 = __half22float2(*(__half2*)&u.x);
            float2 f23 = __half22float2(*(__half2*)&u.y);
            acc.x += c * f01.x; acc.y += c * f01.y;
            acc.z += c * f23.x; acc.w += c * f23.y;
        }
        cnt++;
    }

    float* ps = g_psum + curg * F1 + lane * 4;
    atomicAdd(ps + 0, acc.x); atomicAdd(ps + 1, acc.y);
    atomicAdd(ps + 2, acc.z); atomicAdd(ps + 3, acc.w);
    if (lane == 0) atomicAdd(&g_cnts[curg], (float)cnt);
}

// ---------------- fused: pooled@W2+b2 then heads ----------------
__global__ void k_w2head(const float* __restrict__ W2, const float* __restrict__ b2,
                         const float* __restrict__ Wg, const float* __restrict__ bg,
                         const float* __restrict__ Wf, const float* __restrict__ bf,
                         float* __restrict__ out)
{
    __shared__ float p[F1];
    __shared__ float p2[F2];
    int b = blockIdx.x, t = threadIdx.x;          // 256 threads
    float cnt = g_cnts[b];
    float inv = 1.0f / fmaxf(cnt, 1.0f);
    if (t < F1) p[t] = g_psum[b * F1 + t] * inv;
    __syncthreads();
    float a = (cnt > 0.f) ? b2[t] : 0.0f;         // empty-graph: pooled stays 0
#pragma unroll 4
    for (int d = 0; d < F1; d++) a += p[d] * W2[d * F2 + t];
    p2[t] = a;
    __syncthreads();
    if (t < NGRP) {
        float s = bg[t];
        for (int d = 0; d < F2; d++) s += p2[d] * Wg[d * NGRP + t];
        out[b * NGRP + t] = s;
    } else if (t >= 64 && t < 64 + NGRP * NFAM) {
        int u = t - 64;
        int grp = u / NFAM, f = u - grp * NFAM;
        float s = bf[grp * NFAM + f];
        for (int d = 0; d < F2; d++) s += p2[d] * Wf[(size_t)grp * F2 * NFAM + d * NFAM + f];
        out[NG * NGRP + (size_t)grp * NG * NFAM + b * NFAM + f] = s;
    }
}

// ---------------- launch ----------------
extern "C" void kernel_launch(void* const* d_in, const int* in_sizes, int n_in,
                              void* d_out, int out_size)
{
    const float* x    = (const float*)d_in[0];
    const void*  eidx = d_in[1];
    const void*  batc = d_in[2];
    const float* W1   = (const float*)d_in[3];
    const float* b1   = (const float*)d_in[4];
    const float* W2   = (const float*)d_in[5];
    const float* b2   = (const float*)d_in[6];
    const float* Wg   = (const float*)d_in[7];
    const float* bg   = (const float*)d_in[8];
    const float* Wf   = (const float*)d_in[9];
    const float* bf   = (const float*)d_in[10];
    float* out = (float*)d_out;

    __half *xw1h, *r1h;
    cudaGetSymbolAddress((void**)&xw1h, g_xw1h);
    cudaGetSymbolAddress((void**)&r1h,  g_r1h);

    cudaFuncSetAttribute(k_hgemm, cudaFuncAttributeMaxDynamicSharedMemorySize, HSMEM_BYTES);

    // side stream + events (created once, outside capture; identical launch
    // sequence every call -> deterministic work).
    static cudaStream_t sB = nullptr;
    static cudaEvent_t evFork = nullptr, evDet = nullptr, evJoin = nullptr;
    if (sB == nullptr) {
        cudaStreamCreateWithFlags(&sB, cudaStreamNonBlocking);
        cudaEventCreateWithFlags(&evFork, cudaEventDisableTiming);
        cudaEventCreateWithFlags(&evDet,  cudaEventDisableTiming);
        cudaEventCreateWithFlags(&evJoin, cudaEventDisableTiming);
    }

    // ---- fork: side stream runs GEMM1 (independent of graph build) ----
    cudaEventRecord(evFork, 0);
    cudaStreamWaitEvent(sB, evFork, 0);
    k_hgemm<<<(NN + 127) / 128, 256, HSMEM_BYTES, sB>>>(x, W1, xw1h, NN);

    // ---- main stream: dtype detect + CSR build chain ----
    k_detect<<<1, 32>>>((const unsigned int*)eidx);
    cudaEventRecord(evDet, 0);
    k_init<<<(INIT_N + 255) / 256, 256>>>();
    k_deg<<<(NE / 2 + 255) / 256, 256>>>((const int*)eidx);
    k_scan_local<<<NBLK, SB>>>();
    k_scan_bsum<<<1, 256>>>();
    k_scan_add<<<NBLK, SB>>>();      // also computes dinv + cursor
    k_fill<<<(NE / 2 + 255) / 256, 256>>>((const int*)eidx);

    // side stream: batch convert (needs detect result only)
    cudaStreamWaitEvent(sB, evDet, 0);
    k_conv_batch<<<(NN + 255) / 256, 256, 0, sB>>>((const int*)batc);
    cudaEventRecord(evJoin, sB);

    // ---- join: gathers need xw1h + batch (sB) and CSR (main) ----
    cudaStreamWaitEvent(0, evJoin, 0);

    // layer 1 gather (+relu, fp16 out), then fused layer-2 gather+pool
    k_gather1<<<(NN * 32 + 255) / 256, 256>>>(xw1h, b1, r1h);
    k_gpool<<<(NN + 63) / 64, 256>>>(r1h);

    // fused W2 + heads
    k_w2head<<<NG, 256>>>(W2, b2, Wg, bg, Wf, bf, out);
}